// round 3
// baseline (speedup 1.0000x reference)
#include <cuda_runtime.h>
#include <cuda_fp16.h>
#include <cstdint>

// ============================================================================
// Problem constants:  out[i,j] = w3 . relu(W2 . relu(hx_i + hy_j + b1) + b2) + b3
// B = 512, H = 512, DX = DY = 128
// ============================================================================
#define BB 512
#define HH 512

// Scratch (__device__ globals: allocation-free)
__device__ __align__(128) float  g_hx[BB * HH];   // x@W1[:, :128]^T + b1
__device__ __align__(128) float  g_hy[BB * HH];   // y@W1[:, 128:]^T
__device__ __align__(128) __half g_Whf[HH * HH];  // W2 in fp16, same row-major [n][h]

// ---------------------------------------------------------------------------
// k_main SMEM layout (dynamic, bytes)
// ---------------------------------------------------------------------------
#define OFF_A    0                         // 128 rows x 1024B (fp16, swizzled)
#define OFF_W(s) (131072 + (s) * 32768)    // 2 x (32 rows x 1024B)
#define OFF_B2   196608                    // 512 f32
#define OFF_W3   198656                    // 512 f32
#define SMEM_BYTES 200704

static __device__ __forceinline__ uint32_t smem_u32(const void* p) {
    uint32_t a;
    asm("{ .reg .u64 t; cvta.to.shared.u64 t, %1; cvt.u32.u64 %0, t; }" : "=r"(a) : "l"(p));
    return a;
}
static __device__ __forceinline__ void cp_async_16(uint32_t dst, const void* src) {
    asm volatile("cp.async.cg.shared.global [%0], [%1], 16;" :: "r"(dst), "l"(src) : "memory");
}
static __device__ __forceinline__ void cp_commit() {
    asm volatile("cp.async.commit_group;" ::: "memory");
}
template <int N>
static __device__ __forceinline__ void cp_wait() {
    asm volatile("cp.async.wait_group %0;" :: "n"(N) : "memory");
}
static __device__ __forceinline__ void ldsm_x4(uint32_t& r0, uint32_t& r1, uint32_t& r2,
                                               uint32_t& r3, uint32_t addr) {
    asm volatile("ldmatrix.sync.aligned.m8n8.x4.shared.b16 {%0,%1,%2,%3}, [%4];"
                 : "=r"(r0), "=r"(r1), "=r"(r2), "=r"(r3) : "r"(addr));
}
static __device__ __forceinline__ void mma16816(float* d, const uint32_t* a, const uint32_t* b) {
    asm volatile(
        "mma.sync.aligned.m16n8k16.row.col.f32.f16.f16.f32 "
        "{%0,%1,%2,%3}, {%4,%5,%6,%7}, {%8,%9}, {%0,%1,%2,%3};"
        : "+f"(d[0]), "+f"(d[1]), "+f"(d[2]), "+f"(d[3])
        : "r"(a[0]), "r"(a[1]), "r"(a[2]), "r"(a[3]), "r"(b[0]), "r"(b[1]));
}

// ============================================================================
// Kernel 1: first linear layer (fp32).  grid (16,16,2), block 256
//   path 0: g_hx[i][h] = sum_d x[i,d] * W1[h,d]       + b1[h]
//   path 1: g_hy[j][h] = sum_d y[j,d] * W1[h,128+d]
// ============================================================================
__global__ void __launch_bounds__(256) k_first(const float* __restrict__ x,
                                               const float* __restrict__ y,
                                               const float* __restrict__ W1,
                                               const float* __restrict__ b1) {
    __shared__ float xs_t[128][33];  // [d][i]
    __shared__ float ws[32][128];    // [h][d]
    int path = blockIdx.z;
    const float* src = path ? y : x;
    int i0 = blockIdx.x * 32, h0 = blockIdx.y * 32;
    int colOff = path ? 128 : 0;

    for (int v = threadIdx.x; v < 32 * 128; v += 256) {
        int i = v >> 7, d = v & 127;
        xs_t[d][i] = src[(i0 + i) * 128 + d];
    }
    for (int v = threadIdx.x; v < 32 * 32; v += 256) {
        int r = v >> 5, c4 = v & 31;
        ((float4*)&ws[r][0])[c4] = ((const float4*)&W1[(h0 + r) * 256 + colOff])[c4];
    }
    __syncthreads();

    int ti = threadIdx.x & 31, th = threadIdx.x >> 5;
    float acc0 = 0.f, acc1 = 0.f, acc2 = 0.f, acc3 = 0.f;
    #pragma unroll 4
    for (int d = 0; d < 128; d++) {
        float xv = xs_t[d][ti];
        acc0 = fmaf(xv, ws[th * 4 + 0][d], acc0);
        acc1 = fmaf(xv, ws[th * 4 + 1][d], acc1);
        acc2 = fmaf(xv, ws[th * 4 + 2][d], acc2);
        acc3 = fmaf(xv, ws[th * 4 + 3][d], acc3);
    }
    float* dst = path ? g_hy : g_hx;
    int i = i0 + ti;
    int hb = h0 + th * 4;
    float a0 = path ? 0.f : b1[hb + 0];
    float a1 = path ? 0.f : b1[hb + 1];
    float a2 = path ? 0.f : b1[hb + 2];
    float a3 = path ? 0.f : b1[hb + 3];
    dst[i * HH + hb + 0] = acc0 + a0;
    dst[i * HH + hb + 1] = acc1 + a1;
    dst[i * HH + hb + 2] = acc2 + a2;
    dst[i * HH + hb + 3] = acc3 + a3;
}

// ============================================================================
// Kernel 2: quantize W2 -> fp16, same row-major [n][h] layout.  grid 512, blk 512
// ============================================================================
__global__ void __launch_bounds__(512) k_quant(const float* __restrict__ W2) {
    int idx = blockIdx.x * 512 + threadIdx.x;
    float2 v = ((const float2*)W2)[idx];
    __half2 h;
    h.x = __float2half_rn(v.x);
    h.y = __float2half_rn(v.y);
    ((__half2*)g_Whf)[idx] = h;
}

// ============================================================================
// Kernel 3: main pair-GEMM + fused epilogue.  grid 2048, block 256 (8 warps)
//   CTA tile: 128 pairs (8 i x 16 j), full K = 512, N in 16 chunks of 32.
//   A = relu(hx+hy) fp16 resident in SMEM; W2 fp16 streamed via cp.async.
//   warp grid 4(m) x 2(n): warp tile m32 x n16, mma.m16n8k16 fp32 accum.
// ============================================================================
__global__ void __launch_bounds__(256, 1) k_main(const float* __restrict__ b2g,
                                                 const float* __restrict__ w3g,
                                                 const float* __restrict__ b3g,
                                                 float* __restrict__ out) {
    extern __shared__ __align__(1024) unsigned char smem[];
    uint32_t sb = smem_u32(smem);
    int tid = threadIdx.x, wid = tid >> 5, lane = tid & 31;
    int t = blockIdx.x;
    int i0 = (t >> 5) * 8, j0 = (t & 31) * 16;

    float* b2s = (float*)(smem + OFF_B2);
    float* w3s = (float*)(smem + OFF_W3);

    // ---- b2 / w3 to SMEM ----
    for (int v = tid; v < 512; v += 256) {
        b2s[v] = b2g[v];
        w3s[v] = w3g[v];
    }

    // ---- build A = relu(hx_i + hy_j) fp16, swizzled rows of 1024B ----
    // row p (pair) maps to (i = p/16, j = p%16); 16B chunk index c -> c ^ (p&7)
    for (int idx = tid; idx < 128 * 256; idx += 256) {
        int p = idx >> 8, kk = idx & 255;  // kk indexes half2 pairs (2 h each)
        const float2 hx2 = ((const float2*)(g_hx + (i0 + (p >> 4)) * HH))[kk];
        const float2 hy2 = ((const float2*)(g_hy + (j0 + (p & 15)) * HH))[kk];
        __half2 hv;
        hv.x = __float2half_rn(fmaxf(hx2.x + hy2.x, 0.f));
        hv.y = __float2half_rn(fmaxf(hx2.y + hy2.y, 0.f));
        uint32_t chunk = (uint32_t)(kk >> 2);
        uint32_t addr = sb + OFF_A + (uint32_t)p * 1024 +
                        ((chunk ^ (uint32_t)(p & 7)) << 4) + (uint32_t)(kk & 3) * 4;
        asm volatile("st.shared.b32 [%0], %1;" :: "r"(addr), "r"(*(uint32_t*)&hv) : "memory");
    }

    // ---- W chunk loader: 32 n-rows x 1024B into buffer s, swizzled ----
    // thread -> row n_local = tid/8, 8 consecutive 16B chunks starting (tid%8)*8
    auto issueW = [&](int nc, int s) {
        int n_local = tid >> 3;
        int cbase = (tid & 7) * 8;
        const __half* src = g_Whf + (size_t)(nc * 32 + n_local) * HH + cbase * 8;
        uint32_t dst = sb + OFF_W(s) + (uint32_t)n_local * 1024;
        uint32_t x7 = (uint32_t)(n_local & 7);
        #pragma unroll
        for (int c = 0; c < 8; c++) {
            uint32_t chunk = (uint32_t)(cbase + c);
            cp_async_16(dst + ((chunk ^ x7) << 4), src + c * 8);
        }
    };

    issueW(0, 0);
    cp_commit();

    // ---- per-warp geometry ----
    int wm = wid >> 1;          // 0..3 -> m0 = wm*32
    int wn = wid & 1;           // 0..1 -> n0 = wn*16 (within 32-wide chunk)
    int m0 = wm * 32, n0 = wn * 16;

    // ldmatrix lane address components
    uint32_t aRow0 = (uint32_t)(m0 + (lane & 15)) * 1024;          // mt=0
    uint32_t aRow1 = (uint32_t)(m0 + 16 + (lane & 15)) * 1024;     // mt=1
    uint32_t aHi = (uint32_t)(lane >> 4);                          // k-chunk parity
    uint32_t x7 = (uint32_t)(lane & 7);
    uint32_t bRowOff = (uint32_t)(n0 + (lane & 7) + ((lane >> 4) << 3)) * 1024;
    uint32_t bHi = (uint32_t)((lane >> 3) & 1);

    float rowacc[2][2] = {{0.f, 0.f}, {0.f, 0.f}};  // [mt][row half]

    #pragma unroll 1
    for (int nc = 0; nc < 16; nc++) {
        int s = nc & 1;
        if (nc < 15) {
            issueW(nc + 1, s ^ 1);
            cp_commit();
            cp_wait<1>();
        } else {
            cp_wait<0>();
        }
        __syncthreads();

        uint32_t aBase0 = sb + OFF_A + aRow0;
        uint32_t aBase1 = sb + OFF_A + aRow1;
        uint32_t bBase = sb + OFF_W(s) + bRowOff;

        float d[2][2][4];
        #pragma unroll
        for (int mt = 0; mt < 2; mt++)
            #pragma unroll
            for (int nt = 0; nt < 2; nt++)
                #pragma unroll
                for (int q = 0; q < 4; q++) d[mt][nt][q] = 0.f;

        #pragma unroll 8
        for (int kk = 0; kk < 32; kk++) {
            uint32_t aswz = (((uint32_t)(kk << 1) + aHi) ^ x7) << 4;
            uint32_t bswz = (((uint32_t)(kk << 1) + bHi) ^ x7) << 4;
            uint32_t a0[4], a1[4], b[4];
            ldsm_x4(a0[0], a0[1], a0[2], a0[3], aBase0 + aswz);
            ldsm_x4(a1[0], a1[1], a1[2], a1[3], aBase1 + aswz);
            ldsm_x4(b[0], b[1], b[2], b[3], bBase + bswz);
            mma16816(d[0][0], a0, b + 0);
            mma16816(d[0][1], a0, b + 2);
            mma16816(d[1][0], a1, b + 0);
            mma16816(d[1][1], a1, b + 2);
        }

        // fold: rowacc[mt][rh] += sum_n relu(D + b2[n]) * w3[n]
        int nb = nc * 32 + n0 + (lane & 3) * 2;
        #pragma unroll
        for (int nt = 0; nt < 2; nt++) {
            int c0 = nb + nt * 8, c1 = c0 + 1;
            float bb0 = b2s[c0], bb1 = b2s[c1];
            float ww0 = w3s[c0], ww1 = w3s[c1];
            #pragma unroll
            for (int mt = 0; mt < 2; mt++) {
                rowacc[mt][0] = fmaf(fmaxf(d[mt][nt][0] + bb0, 0.f), ww0, rowacc[mt][0]);
                rowacc[mt][0] = fmaf(fmaxf(d[mt][nt][1] + bb1, 0.f), ww1, rowacc[mt][0]);
                rowacc[mt][1] = fmaf(fmaxf(d[mt][nt][2] + bb0, 0.f), ww0, rowacc[mt][1]);
                rowacc[mt][1] = fmaf(fmaxf(d[mt][nt][3] + bb1, 0.f), ww1, rowacc[mt][1]);
            }
        }
        __syncthreads();
    }

    // ---- reduce across the 4 lanes sharing each row, then across 2 n-warps ----
    #pragma unroll
    for (int mt = 0; mt < 2; mt++)
        #pragma unroll
        for (int rh = 0; rh < 2; rh++) {
            rowacc[mt][rh] += __shfl_xor_sync(0xFFFFFFFFu, rowacc[mt][rh], 1);
            rowacc[mt][rh] += __shfl_xor_sync(0xFFFFFFFFu, rowacc[mt][rh], 2);
        }

    float* part = (float*)(smem + OFF_W(0));  // reuse: [128][2]
    if ((lane & 3) == 0) {
        int g = lane >> 2;
        #pragma unroll
        for (int mt = 0; mt < 2; mt++)
            #pragma unroll
            for (int rh = 0; rh < 2; rh++) {
                int m = m0 + mt * 16 + rh * 8 + g;
                part[m * 2 + wn] = rowacc[mt][rh];
            }
    }
    __syncthreads();

    if (tid < 128) {
        float res = part[tid * 2 + 0] + part[tid * 2 + 1] + b3g[0];
        int i = i0 + (tid >> 4);
        int j = j0 + (tid & 15);
        out[i * BB + j] = res;
    }
}

// ============================================================================
// Host launcher
// ============================================================================
extern "C" void kernel_launch(void* const* d_in, const int* in_sizes, int n_in,
                              void* d_out, int out_size) {
    const float* x  = (const float*)d_in[0];
    const float* y  = (const float*)d_in[1];
    const float* W1 = (const float*)d_in[2];
    const float* b1 = (const float*)d_in[3];
    const float* W2 = (const float*)d_in[4];
    const float* b2 = (const float*)d_in[5];
    const float* W3 = (const float*)d_in[6];
    const float* b3 = (const float*)d_in[7];
    float* out = (float*)d_out;

    cudaFuncSetAttribute(k_main, cudaFuncAttributeMaxDynamicSharedMemorySize, SMEM_BYTES);

    k_first<<<dim3(16, 16, 2), 256>>>(x, y, W1, b1);
    k_quant<<<512, 512>>>(W2);
    k_main<<<2048, 256, SMEM_BYTES>>>(b2, W3, b3, out);
}

// round 4
// speedup vs baseline: 1.1425x; 1.1425x over previous
#include <cuda_runtime.h>
#include <cuda_fp16.h>
#include <cstdint>

// ============================================================================
// out[i,j] = w3 . relu(W2 . relu(hx_i + hy_j + b1) + b2) + b3
// B = 512, H = 512, DX = DY = 128
// ============================================================================
#define BB 512
#define HH 512

__device__ __align__(128) float  g_hx[BB * HH];   // x@W1[:, :128]^T + b1
__device__ __align__(128) float  g_hy[BB * HH];   // y@W1[:, 128:]^T
__device__ __align__(128) __half g_Whf[HH * HH];  // W2 fp16 row-major [n][h]

// k_main SMEM layout (dynamic, bytes)
#define OFF_A    0                         // 128 rows x 1024B (fp16, swizzled)
#define OFF_W(s) (131072 + (s) * 32768)    // 2 x (64 rows x 512B: n64 x k256)
#define OFF_B2   196608                    // 512 f32
#define OFF_W3   198656                    // 512 f32
#define SMEM_BYTES 200704

static __device__ __forceinline__ uint32_t smem_u32(const void* p) {
    uint32_t a;
    asm("{ .reg .u64 t; cvta.to.shared.u64 t, %1; cvt.u32.u64 %0, t; }" : "=r"(a) : "l"(p));
    return a;
}
static __device__ __forceinline__ void cp_async_16(uint32_t dst, const void* src) {
    asm volatile("cp.async.cg.shared.global [%0], [%1], 16;" :: "r"(dst), "l"(src) : "memory");
}
static __device__ __forceinline__ void cp_commit() {
    asm volatile("cp.async.commit_group;" ::: "memory");
}
template <int N>
static __device__ __forceinline__ void cp_wait() {
    asm volatile("cp.async.wait_group %0;" :: "n"(N) : "memory");
}
static __device__ __forceinline__ void ldsm_x4(uint32_t& r0, uint32_t& r1, uint32_t& r2,
                                               uint32_t& r3, uint32_t addr) {
    asm volatile("ldmatrix.sync.aligned.m8n8.x4.shared.b16 {%0,%1,%2,%3}, [%4];"
                 : "=r"(r0), "=r"(r1), "=r"(r2), "=r"(r3) : "r"(addr));
}
static __device__ __forceinline__ void mma16816(float* d, const uint32_t* a, const uint32_t* b) {
    asm volatile(
        "mma.sync.aligned.m16n8k16.row.col.f32.f16.f16.f32 "
        "{%0,%1,%2,%3}, {%4,%5,%6,%7}, {%8,%9}, {%0,%1,%2,%3};"
        : "+f"(d[0]), "+f"(d[1]), "+f"(d[2]), "+f"(d[3])
        : "r"(a[0]), "r"(a[1]), "r"(a[2]), "r"(a[3]), "r"(b[0]), "r"(b[1]));
}

// ============================================================================
// Kernel 1: first linear layer (fp32).  grid (16,16,2), block 256
// ============================================================================
__global__ void __launch_bounds__(256) k_first(const float* __restrict__ x,
                                               const float* __restrict__ y,
                                               const float* __restrict__ W1,
                                               const float* __restrict__ b1) {
    __shared__ float xs_t[128][33];
    __shared__ float ws[32][128];
    int path = blockIdx.z;
    const float* src = path ? y : x;
    int i0 = blockIdx.x * 32, h0 = blockIdx.y * 32;
    int colOff = path ? 128 : 0;

    for (int v = threadIdx.x; v < 32 * 128; v += 256) {
        int i = v >> 7, d = v & 127;
        xs_t[d][i] = src[(i0 + i) * 128 + d];
    }
    for (int v = threadIdx.x; v < 32 * 32; v += 256) {
        int r = v >> 5, c4 = v & 31;
        ((float4*)&ws[r][0])[c4] = ((const float4*)&W1[(h0 + r) * 256 + colOff])[c4];
    }
    __syncthreads();

    int ti = threadIdx.x & 31, th = threadIdx.x >> 5;
    float acc0 = 0.f, acc1 = 0.f, acc2 = 0.f, acc3 = 0.f;
    #pragma unroll 4
    for (int d = 0; d < 128; d++) {
        float xv = xs_t[d][ti];
        acc0 = fmaf(xv, ws[th * 4 + 0][d], acc0);
        acc1 = fmaf(xv, ws[th * 4 + 1][d], acc1);
        acc2 = fmaf(xv, ws[th * 4 + 2][d], acc2);
        acc3 = fmaf(xv, ws[th * 4 + 3][d], acc3);
    }
    float* dst = path ? g_hy : g_hx;
    int i = i0 + ti;
    int hb = h0 + th * 4;
    float a0 = path ? 0.f : b1[hb + 0];
    float a1 = path ? 0.f : b1[hb + 1];
    float a2 = path ? 0.f : b1[hb + 2];
    float a3 = path ? 0.f : b1[hb + 3];
    dst[i * HH + hb + 0] = acc0 + a0;
    dst[i * HH + hb + 1] = acc1 + a1;
    dst[i * HH + hb + 2] = acc2 + a2;
    dst[i * HH + hb + 3] = acc3 + a3;
}

// ============================================================================
// Kernel 2: quantize W2 -> fp16 row-major.  grid 512, blk 512
// ============================================================================
__global__ void __launch_bounds__(512) k_quant(const float* __restrict__ W2) {
    int idx = blockIdx.x * 512 + threadIdx.x;
    float2 v = ((const float2*)W2)[idx];
    __half2 h;
    h.x = __float2half_rn(v.x);
    h.y = __float2half_rn(v.y);
    ((__half2*)g_Whf)[idx] = h;
}

// ============================================================================
// Kernel 3: main pair-GEMM + fused epilogue.  grid 2048, block 256 (8 warps)
//   CTA tile: 128 pairs (8i x 16j).  N in 8 chunks of 64; each chunk in two
//   k256 halves (16 pipeline steps of 32KB W).  Warp grid 4m x 2n, warp tile
//   m32 x n32, D (32 regs) persists across k-halves; fused fold after kh=1.
// ============================================================================
__global__ void __launch_bounds__(256, 1) k_main(const float* __restrict__ b2g,
                                                 const float* __restrict__ w3g,
                                                 const float* __restrict__ b3g,
                                                 float* __restrict__ out) {
    extern __shared__ __align__(1024) unsigned char smem[];
    uint32_t sb = smem_u32(smem);
    int tid = threadIdx.x, wid = tid >> 5, lane = tid & 31;
    int t = blockIdx.x;
    int i0 = (t >> 5) * 8, j0 = (t & 31) * 16;

    float* b2s = (float*)(smem + OFF_B2);
    float* w3s = (float*)(smem + OFF_W3);

    // ---- W step loader: step st -> (nc = st/2, kh = st&1), 64 rows x 512B ----
    auto issueW = [&](int st, int s) {
        int n_local = tid >> 2;         // 0..63, 4 threads per row
        int cbase = (tid & 3) * 8;      // 8 x 16B chunks per thread
        int nc = st >> 1, kh = st & 1;
        const __half* src = g_Whf + (size_t)(nc * 64 + n_local) * HH + kh * 256 + cbase * 8;
        uint32_t dst = sb + OFF_W(s) + (uint32_t)n_local * 512;
        uint32_t xr = (uint32_t)(n_local & 7);
        #pragma unroll
        for (int c = 0; c < 8; c++) {
            uint32_t chunk = (uint32_t)(cbase + c);
            cp_async_16(dst + ((chunk ^ xr) << 4), src + c * 8);
        }
    };

    issueW(0, 0);
    cp_commit();

    // ---- b2 / w3 to SMEM ----
    for (int v = tid; v < 512; v += 256) {
        b2s[v] = b2g[v];
        w3s[v] = w3g[v];
    }

    // ---- build A = relu(hx_i + hy_j) fp16, swizzled rows of 1024B ----
    for (int idx = tid; idx < 128 * 256; idx += 256) {
        int p = idx >> 8, kk = idx & 255;
        const float2 hx2 = ((const float2*)(g_hx + (i0 + (p >> 4)) * HH))[kk];
        const float2 hy2 = ((const float2*)(g_hy + (j0 + (p & 15)) * HH))[kk];
        __half2 hv;
        hv.x = __float2half_rn(fmaxf(hx2.x + hy2.x, 0.f));
        hv.y = __float2half_rn(fmaxf(hx2.y + hy2.y, 0.f));
        uint32_t chunk = (uint32_t)(kk >> 2);
        uint32_t addr = sb + OFF_A + (uint32_t)p * 1024 +
                        ((chunk ^ (uint32_t)(p & 7)) << 4) + (uint32_t)(kk & 3) * 4;
        asm volatile("st.shared.b32 [%0], %1;" :: "r"(addr), "r"(*(uint32_t*)&hv) : "memory");
    }

    // ---- per-warp geometry: warp tile m32 x n32 ----
    int wm = wid >> 1;          // 0..3 -> m0 = wm*32
    int wn = wid & 1;           // 0..1 -> n0 = wn*32 within 64-chunk
    int m0 = wm * 32, n0 = wn * 32;

    uint32_t x7 = (uint32_t)(lane & 7);
    uint32_t aRow0 = sb + OFF_A + (uint32_t)(m0 + (lane & 15)) * 1024;
    uint32_t aRow1 = aRow0 + 16 * 1024;
    uint32_t aHi = (uint32_t)(lane >> 4);
    uint32_t bRow0 = (uint32_t)(n0 + (lane & 7) + ((lane >> 4) << 3)) * 512;
    uint32_t bRow1 = bRow0 + 16 * 512;
    uint32_t bHi = (uint32_t)((lane >> 3) & 1);

    float d[2][4][4];                                // [mt][nt][q]
    float rowacc[2][2] = {{0.f, 0.f}, {0.f, 0.f}};   // [mt][row half]

    #pragma unroll 1
    for (int st = 0; st < 16; st++) {
        int s = st & 1, kh = st & 1;
        if (st < 15) {
            issueW(st + 1, s ^ 1);
            cp_commit();
            cp_wait<1>();
        } else {
            cp_wait<0>();
        }
        __syncthreads();

        if (kh == 0) {
            #pragma unroll
            for (int mt = 0; mt < 2; mt++)
                #pragma unroll
                for (int nt = 0; nt < 4; nt++)
                    #pragma unroll
                    for (int q = 0; q < 4; q++) d[mt][nt][q] = 0.f;
        }

        uint32_t bBase0 = sb + OFF_W(s) + bRow0;
        uint32_t bBase1 = sb + OFF_W(s) + bRow1;
        uint32_t aChunkBase = (uint32_t)(kh * 32);

        #pragma unroll 8
        for (int kk = 0; kk < 16; kk++) {
            uint32_t aswz = (((aChunkBase + (uint32_t)(kk << 1) + aHi) ^ x7) << 4);
            uint32_t bswz = ((((uint32_t)(kk << 1) + bHi) ^ x7) << 4);
            uint32_t a0[4], a1[4], b0[4], b1[4];
            ldsm_x4(a0[0], a0[1], a0[2], a0[3], aRow0 + aswz);
            ldsm_x4(a1[0], a1[1], a1[2], a1[3], aRow1 + aswz);
            ldsm_x4(b0[0], b0[1], b0[2], b0[3], bBase0 + bswz);
            ldsm_x4(b1[0], b1[1], b1[2], b1[3], bBase1 + bswz);
            mma16816(d[0][0], a0, b0 + 0);
            mma16816(d[0][1], a0, b0 + 2);
            mma16816(d[0][2], a0, b1 + 0);
            mma16816(d[0][3], a0, b1 + 2);
            mma16816(d[1][0], a1, b0 + 0);
            mma16816(d[1][1], a1, b0 + 2);
            mma16816(d[1][2], a1, b1 + 0);
            mma16816(d[1][3], a1, b1 + 2);
        }

        if (kh == 1) {
            // fold: rowacc += sum_n relu(D + b2[n]) * w3[n]
            int ncol = (st >> 1) * 64 + n0 + (lane & 3) * 2;
            #pragma unroll
            for (int nt = 0; nt < 4; nt++) {
                int c0 = ncol + nt * 8, c1 = c0 + 1;
                float bb0 = b2s[c0], bb1 = b2s[c1];
                float ww0 = w3s[c0], ww1 = w3s[c1];
                #pragma unroll
                for (int mt = 0; mt < 2; mt++) {
                    rowacc[mt][0] = fmaf(fmaxf(d[mt][nt][0] + bb0, 0.f), ww0, rowacc[mt][0]);
                    rowacc[mt][0] = fmaf(fmaxf(d[mt][nt][1] + bb1, 0.f), ww1, rowacc[mt][0]);
                    rowacc[mt][1] = fmaf(fmaxf(d[mt][nt][2] + bb0, 0.f), ww0, rowacc[mt][1]);
                    rowacc[mt][1] = fmaf(fmaxf(d[mt][nt][3] + bb1, 0.f), ww1, rowacc[mt][1]);
                }
            }
        }
        __syncthreads();
    }

    // ---- reduce across 4 lanes sharing each row, then across 2 n-warps ----
    #pragma unroll
    for (int mt = 0; mt < 2; mt++)
        #pragma unroll
        for (int rh = 0; rh < 2; rh++) {
            rowacc[mt][rh] += __shfl_xor_sync(0xFFFFFFFFu, rowacc[mt][rh], 1);
            rowacc[mt][rh] += __shfl_xor_sync(0xFFFFFFFFu, rowacc[mt][rh], 2);
        }

    float* part = (float*)(smem + OFF_W(0));  // reuse: [128][2]
    if ((lane & 3) == 0) {
        int g = lane >> 2;
        #pragma unroll
        for (int mt = 0; mt < 2; mt++)
            #pragma unroll
            for (int rh = 0; rh < 2; rh++) {
                int m = m0 + mt * 16 + rh * 8 + g;
                part[m * 2 + wn] = rowacc[mt][rh];
            }
    }
    __syncthreads();

    if (tid < 128) {
        float res = part[tid * 2 + 0] + part[tid * 2 + 1] + b3g[0];
        int i = i0 + (tid >> 4);
        int j = j0 + (tid & 15);
        out[i * BB + j] = res;
    }
}

// ============================================================================
// Host launcher
// ============================================================================
extern "C" void kernel_launch(void* const* d_in, const int* in_sizes, int n_in,
                              void* d_out, int out_size) {
    const float* x  = (const float*)d_in[0];
    const float* y  = (const float*)d_in[1];
    const float* W1 = (const float*)d_in[2];
    const float* b1 = (const float*)d_in[3];
    const float* W2 = (const float*)d_in[4];
    const float* b2 = (const float*)d_in[5];
    const float* W3 = (const float*)d_in[6];
    const float* b3 = (const float*)d_in[7];
    float* out = (float*)d_out;

    cudaFuncSetAttribute(k_main, cudaFuncAttributeMaxDynamicSharedMemorySize, SMEM_BYTES);

    k_first<<<dim3(16, 16, 2), 256>>>(x, y, W1, b1);
    k_quant<<<512, 512>>>(W2);
    k_main<<<2048, 256, SMEM_BYTES>>>(b2, W3, b3, out);
}

// round 5
// speedup vs baseline: 1.7090x; 1.4959x over previous
#include <cuda_runtime.h>
#include <cuda_fp16.h>
#include <cstdint>

// ============================================================================
// out[i,j] = w3 . relu(W2 . relu(hx_i + hy_j + b1) + b2) + b3
// B = 512, H = 512, DX = DY = 128
// ============================================================================
#define BB 512
#define HH 512

__device__ __align__(128)  float  g_hx[BB * HH];           // x@W1[:, :128]^T + b1
__device__ __align__(128)  float  g_hy[BB * HH];           // y@W1[:, 128:]^T
// W2 fp16, pre-swizzled step-major: 16 steps (nc*4+kq) of 32KB.
// step slab: row n_local (0..127) * 256B; 16B chunk c at ((c ^ (n_local&7))<<4).
__device__ __align__(1024) unsigned char g_Wsw[HH * HH * 2];

// k_main SMEM layout (dynamic, bytes)
#define OFF_A    0                         // 128 rows x 1024B (fp16, swizzled)
#define OFF_W(s) (131072 + (s) * 32768)    // 2 x 32KB W slabs
#define OFF_B2   196608                    // 512 f32
#define OFF_W3   198656                    // 512 f32
#define OFF_MB   200704                    // 2 mbarriers
#define SMEM_BYTES 200832

static __device__ __forceinline__ uint32_t smem_u32(const void* p) {
    uint32_t a;
    asm("{ .reg .u64 t; cvta.to.shared.u64 t, %1; cvt.u32.u64 %0, t; }" : "=r"(a) : "l"(p));
    return a;
}
#define MBAR_INIT(addr, cnt) \
    asm volatile("mbarrier.init.shared.b64 [%0], %1;" :: "r"(addr), "r"(cnt) : "memory")
#define MBAR_EXPECT_TX(addr, bytes) \
    asm volatile("mbarrier.arrive.expect_tx.shared.b64 _, [%0], %1;" :: "r"(addr), "r"(bytes) : "memory")
#define MBAR_WAIT(addr, ph) do {                                                \
    uint32_t _m = (addr), _p = (ph), _d;                                        \
    asm volatile("{\n\t.reg .pred p;\n\t"                                       \
        "mbarrier.try_wait.parity.acquire.cta.shared::cta.b64 p, [%1], %2;\n\t" \
        "selp.b32 %0, 1, 0, p;\n\t}" : "=r"(_d) : "r"(_m), "r"(_p) : "memory"); \
    if (!_d) {                                                                  \
        asm volatile("{\n\t.reg .pred P;\n\tWL%=:\n\t"                          \
            "mbarrier.try_wait.parity.acquire.cta.shared::cta.b64 P, [%0], %1, 0x989680;\n\t" \
            "@P bra.uni WD%=;\n\tbra.uni WL%=;\n\tWD%=:\n\t}"                   \
            :: "r"(_m), "r"(_p) : "memory");                                    \
    }                                                                           \
} while (0)
static __device__ __forceinline__ void bulk_g2s(uint32_t dst, const void* src,
                                                uint32_t bytes, uint32_t mbar) {
    asm volatile(
        "cp.async.bulk.shared::cluster.global.mbarrier::complete_tx::bytes [%0], [%1], %2, [%3];"
        :: "r"(dst), "l"(src), "r"(bytes), "r"(mbar) : "memory");
}
static __device__ __forceinline__ void ldsm_x4(uint32_t& r0, uint32_t& r1, uint32_t& r2,
                                               uint32_t& r3, uint32_t addr) {
    asm volatile("ldmatrix.sync.aligned.m8n8.x4.shared.b16 {%0,%1,%2,%3}, [%4];"
                 : "=r"(r0), "=r"(r1), "=r"(r2), "=r"(r3) : "r"(addr));
}
static __device__ __forceinline__ void mma16816(float* d, const uint32_t* a, const uint32_t* b) {
    asm volatile(
        "mma.sync.aligned.m16n8k16.row.col.f32.f16.f16.f32 "
        "{%0,%1,%2,%3}, {%4,%5,%6,%7}, {%8,%9}, {%0,%1,%2,%3};"
        : "+f"(d[0]), "+f"(d[1]), "+f"(d[2]), "+f"(d[3])
        : "r"(a[0]), "r"(a[1]), "r"(a[2]), "r"(a[3]), "r"(b[0]), "r"(b[1]));
}

// ============================================================================
// Kernel 1: prep = first linear (blocks 0..511) + W2 quant/swizzle (512..1023)
// ============================================================================
__global__ void __launch_bounds__(256) k_prep(const float* __restrict__ x,
                                              const float* __restrict__ y,
                                              const float* __restrict__ W1,
                                              const float* __restrict__ b1,
                                              const float* __restrict__ W2) {
    int b = blockIdx.x;
    if (b >= 512) {
        // ---- quant: 2 consecutive h per thread ----
        int idx = ((b - 512) * 256 + threadIdx.x) * 2;
        int n = idx >> 9, h = idx & 511;
        int nc = n >> 7, n_local = n & 127;
        int kq = h >> 7, k_local = h & 127;
        int step = nc * 4 + kq;
        uint32_t c = (uint32_t)(k_local >> 3);
        uint32_t off = (uint32_t)n_local * 256 +
                       ((c ^ (uint32_t)(n_local & 7)) << 4) + (uint32_t)(k_local & 7) * 2;
        float2 v = *(const float2*)(W2 + (size_t)n * HH + h);
        __half2 hv;
        hv.x = __float2half_rn(v.x);
        hv.y = __float2half_rn(v.y);
        *(uint32_t*)(g_Wsw + (size_t)step * 32768 + off) = *(uint32_t*)&hv;
        return;
    }
    // ---- first linear ----
    __shared__ float xs_t[128][33];
    __shared__ float ws[32][128];
    int path = b >> 8;
    int rem = b & 255;
    int i0 = (rem & 15) * 32, h0 = (rem >> 4) * 32;
    const float* src = path ? y : x;
    int colOff = path ? 128 : 0;

    for (int v = threadIdx.x; v < 32 * 128; v += 256) {
        int i = v >> 7, d = v & 127;
        xs_t[d][i] = src[(i0 + i) * 128 + d];
    }
    for (int v = threadIdx.x; v < 32 * 32; v += 256) {
        int r = v >> 5, c4 = v & 31;
        ((float4*)&ws[r][0])[c4] = ((const float4*)&W1[(h0 + r) * 256 + colOff])[c4];
    }
    __syncthreads();

    int ti = threadIdx.x & 31, th = threadIdx.x >> 5;
    float acc0 = 0.f, acc1 = 0.f, acc2 = 0.f, acc3 = 0.f;
    #pragma unroll 4
    for (int d = 0; d < 128; d++) {
        float xv = xs_t[d][ti];
        acc0 = fmaf(xv, ws[th * 4 + 0][d], acc0);
        acc1 = fmaf(xv, ws[th * 4 + 1][d], acc1);
        acc2 = fmaf(xv, ws[th * 4 + 2][d], acc2);
        acc3 = fmaf(xv, ws[th * 4 + 3][d], acc3);
    }
    float* dst = path ? g_hy : g_hx;
    int i = i0 + ti;
    int hb = h0 + th * 4;
    float a0 = path ? 0.f : b1[hb + 0];
    float a1 = path ? 0.f : b1[hb + 1];
    float a2 = path ? 0.f : b1[hb + 2];
    float a3 = path ? 0.f : b1[hb + 3];
    dst[i * HH + hb + 0] = acc0 + a0;
    dst[i * HH + hb + 1] = acc1 + a1;
    dst[i * HH + hb + 2] = acc2 + a2;
    dst[i * HH + hb + 3] = acc3 + a3;
}

// ============================================================================
// Kernel 2: main pair-GEMM + fused epilogue.  grid 2048, block 256 (8 warps)
//   CTA tile: 128 pairs (8i x 16j).  N in 4 chunks of 128; K in 4 quarters of
//   128 -> 16 steps of 32KB W, streamed via cp.async.bulk (2-deep, mbarrier).
//   Warp grid 2m x 4n, warp tile m64 x n32; fold after kq==3.
// ============================================================================
__global__ void __launch_bounds__(256, 1) k_main(const float* __restrict__ b2g,
                                                 const float* __restrict__ w3g,
                                                 const float* __restrict__ b3g,
                                                 float* __restrict__ out) {
    extern __shared__ __align__(1024) unsigned char smem[];
    uint32_t sb = smem_u32(smem);
    int tid = threadIdx.x, wid = tid >> 5, lane = tid & 31;
    int t = blockIdx.x;
    int i0 = (t >> 5) * 8, j0 = (t & 31) * 16;

    float* b2s = (float*)(smem + OFF_B2);
    float* w3s = (float*)(smem + OFF_W3);

    // ---- init mbarriers + kick off first two W slabs (overlap with A build) ----
    if (tid == 0) {
        MBAR_INIT(sb + OFF_MB + 0, 1);
        MBAR_INIT(sb + OFF_MB + 8, 1);
        asm volatile("fence.proxy.async.shared::cta;" ::: "memory");
        MBAR_EXPECT_TX(sb + OFF_MB + 0, 32768u);
        bulk_g2s(sb + OFF_W(0), g_Wsw + 0 * 32768, 32768u, sb + OFF_MB + 0);
        MBAR_EXPECT_TX(sb + OFF_MB + 8, 32768u);
        bulk_g2s(sb + OFF_W(1), g_Wsw + 1 * 32768, 32768u, sb + OFF_MB + 8);
    }

    // ---- b2 / w3 to SMEM ----
    for (int v = tid; v < 512; v += 256) {
        b2s[v] = b2g[v];
        w3s[v] = w3g[v];
    }

    // ---- build A = relu(hx_i + hy_j) fp16, swizzled rows of 1024B ----
    for (int idx = tid; idx < 128 * 256; idx += 256) {
        int p = idx >> 8, kk = idx & 255;
        const float2 hx2 = ((const float2*)(g_hx + (i0 + (p >> 4)) * HH))[kk];
        const float2 hy2 = ((const float2*)(g_hy + (j0 + (p & 15)) * HH))[kk];
        __half2 hv;
        hv.x = __float2half_rn(fmaxf(hx2.x + hy2.x, 0.f));
        hv.y = __float2half_rn(fmaxf(hx2.y + hy2.y, 0.f));
        uint32_t chunk = (uint32_t)(kk >> 2);
        uint32_t addr = sb + OFF_A + (uint32_t)p * 1024 +
                        ((chunk ^ (uint32_t)(p & 7)) << 4) + (uint32_t)(kk & 3) * 4;
        asm volatile("st.shared.b32 [%0], %1;" :: "r"(addr), "r"(*(uint32_t*)&hv) : "memory");
    }
    __syncthreads();   // A ready; mbarrier inits visible

    // ---- per-warp geometry: warp tile m64 x n32 ----
    int wm = wid >> 2;          // 0..1 -> m0 = wm*64
    int wn = wid & 3;           // 0..3 -> n0 = wn*32 within 128-chunk
    int m0 = wm * 64, n0 = wn * 32;

    uint32_t x7 = (uint32_t)(lane & 7);
    uint32_t aHi = (uint32_t)(lane >> 4);
    uint32_t aRow[4];
    #pragma unroll
    for (int mi = 0; mi < 4; mi++)
        aRow[mi] = sb + OFF_A + (uint32_t)(m0 + mi * 16 + (lane & 15)) * 1024;
    uint32_t bRowOff = (uint32_t)(n0 + (lane & 7) + ((lane >> 4) << 3)) * 256;
    uint32_t bHi = (uint32_t)((lane >> 3) & 1);

    float d[4][4][4];                 // [mi][ni][q]
    float rowacc[4][2];               // [mi][row half]
    #pragma unroll
    for (int mi = 0; mi < 4; mi++) { rowacc[mi][0] = 0.f; rowacc[mi][1] = 0.f; }

    #pragma unroll 1
    for (int st = 0; st < 16; st++) {
        int s = st & 1, kq = st & 3;
        MBAR_WAIT(sb + OFF_MB + s * 8, (st >> 1) & 1);

        if (kq == 0) {
            #pragma unroll
            for (int mi = 0; mi < 4; mi++)
                #pragma unroll
                for (int ni = 0; ni < 4; ni++)
                    #pragma unroll
                    for (int q = 0; q < 4; q++) d[mi][ni][q] = 0.f;
        }

        uint32_t bBase = sb + OFF_W(s) + bRowOff;
        uint32_t aChunk0 = (uint32_t)(kq * 16);

        #pragma unroll
        for (int kk = 0; kk < 8; kk++) {
            uint32_t aswz = (((aChunk0 + (uint32_t)(kk << 1) + aHi) ^ x7) << 4);
            uint32_t bswz = ((((uint32_t)(kk << 1) + bHi) ^ x7) << 4);
            uint32_t a[4][4], b0[4], b1[4];
            #pragma unroll
            for (int mi = 0; mi < 4; mi++)
                ldsm_x4(a[mi][0], a[mi][1], a[mi][2], a[mi][3], aRow[mi] + aswz);
            ldsm_x4(b0[0], b0[1], b0[2], b0[3], bBase + bswz);
            ldsm_x4(b1[0], b1[1], b1[2], b1[3], bBase + 16 * 256 + bswz);
            #pragma unroll
            for (int mi = 0; mi < 4; mi++) {
                mma16816(d[mi][0], a[mi], b0 + 0);
                mma16816(d[mi][1], a[mi], b0 + 2);
                mma16816(d[mi][2], a[mi], b1 + 0);
                mma16816(d[mi][3], a[mi], b1 + 2);
            }
        }

        if (kq == 3) {
            // fold: rowacc += sum_n relu(D + b2[n]) * w3[n]
            int ncol = (st >> 2) * 128 + n0 + (lane & 3) * 2;
            #pragma unroll
            for (int ni = 0; ni < 4; ni++) {
                int c0 = ncol + ni * 8, c1 = c0 + 1;
                float bb0 = b2s[c0], bb1 = b2s[c1];
                float ww0 = w3s[c0], ww1 = w3s[c1];
                #pragma unroll
                for (int mi = 0; mi < 4; mi++) {
                    rowacc[mi][0] = fmaf(fmaxf(d[mi][ni][0] + bb0, 0.f), ww0, rowacc[mi][0]);
                    rowacc[mi][0] = fmaf(fmaxf(d[mi][ni][1] + bb1, 0.f), ww1, rowacc[mi][0]);
                    rowacc[mi][1] = fmaf(fmaxf(d[mi][ni][2] + bb0, 0.f), ww0, rowacc[mi][1]);
                    rowacc[mi][1] = fmaf(fmaxf(d[mi][ni][3] + bb1, 0.f), ww1, rowacc[mi][1]);
                }
            }
        }
        __syncthreads();   // all warps done with W[s]
        if (tid == 0 && st + 2 < 16) {
            MBAR_EXPECT_TX(sb + OFF_MB + s * 8, 32768u);
            bulk_g2s(sb + OFF_W(s), g_Wsw + (size_t)(st + 2) * 32768, 32768u,
                     sb + OFF_MB + s * 8);
        }
    }

    // ---- reduce across 4 lanes sharing each row, then across 4 n-warps ----
    #pragma unroll
    for (int mi = 0; mi < 4; mi++)
        #pragma unroll
        for (int rh = 0; rh < 2; rh++) {
            rowacc[mi][rh] += __shfl_xor_sync(0xFFFFFFFFu, rowacc[mi][rh], 1);
            rowacc[mi][rh] += __shfl_xor_sync(0xFFFFFFFFu, rowacc[mi][rh], 2);
        }

    float* part = (float*)(smem + OFF_W(0));  // reuse: [128][4]
    if ((lane & 3) == 0) {
        int g = lane >> 2;
        #pragma unroll
        for (int mi = 0; mi < 4; mi++)
            #pragma unroll
            for (int rh = 0; rh < 2; rh++) {
                int m = m0 + mi * 16 + rh * 8 + g;
                part[m * 4 + wn] = rowacc[mi][rh];
            }
    }
    __syncthreads();

    if (tid < 128) {
        float res = part[tid * 4 + 0] + part[tid * 4 + 1] +
                    part[tid * 4 + 2] + part[tid * 4 + 3] + b3g[0];
        int i = i0 + (tid >> 4);
        int j = j0 + (tid & 15);
        out[i * BB + j] = res;
    }
}

// ============================================================================
// Host launcher
// ============================================================================
extern "C" void kernel_launch(void* const* d_in, const int* in_sizes, int n_in,
                              void* d_out, int out_size) {
    const float* x  = (const float*)d_in[0];
    const float* y  = (const float*)d_in[1];
    const float* W1 = (const float*)d_in[2];
    const float* b1 = (const float*)d_in[3];
    const float* W2 = (const float*)d_in[4];
    const float* b2 = (const float*)d_in[5];
    const float* W3 = (const float*)d_in[6];
    const float* b3 = (const float*)d_in[7];
    float* out = (float*)d_out;

    cudaFuncSetAttribute(k_main, cudaFuncAttributeMaxDynamicSharedMemorySize, SMEM_BYTES);

    k_prep<<<1024, 256>>>(x, y, W1, b1, W2);
    k_main<<<2048, 256, SMEM_BYTES>>>(b2, W3, b3, out);
}

// round 6
// speedup vs baseline: 2.3427x; 1.3708x over previous
#include <cuda_runtime.h>
#include <cuda_fp16.h>
#include <cstdint>

// ============================================================================
// out[i,j] = w3 . relu(W2 . relu(hx_i + hy_j + b1) + b2) + b3
// B = 512, H = 512, DX = DY = 128
// ============================================================================
#define BB 512
#define HH 512

__device__ __align__(128)  float  g_hx[BB * HH];           // x@W1[:, :128]^T + b1
__device__ __align__(128)  float  g_hy[BB * HH];           // y@W1[:, 128:]^T
// W2 fp16, pre-swizzled step-major: 16 steps (nc*4+kq) of 32KB.
__device__ __align__(1024) unsigned char g_Wsw[HH * HH * 2];

// k_main SMEM layout (dynamic, bytes)
#define OFF_A    0                         // 128 rows x 1024B (fp16, swizzled)
#define OFF_W(s) (131072 + (s) * 32768)    // 2 x 32KB W slabs
#define OFF_B2   196608                    // 512 f32
#define OFF_W3   198656                    // 512 f32
#define OFF_MB   200704                    // 2 mbarriers (16B) + 2 counters (8B)
#define SMEM_BYTES 200832

static __device__ __forceinline__ uint32_t smem_u32(const void* p) {
    uint32_t a;
    asm("{ .reg .u64 t; cvta.to.shared.u64 t, %1; cvt.u32.u64 %0, t; }" : "=r"(a) : "l"(p));
    return a;
}
#define MBAR_INIT(addr, cnt) \
    asm volatile("mbarrier.init.shared.b64 [%0], %1;" :: "r"(addr), "r"(cnt) : "memory")
#define MBAR_EXPECT_TX(addr, bytes) \
    asm volatile("mbarrier.arrive.expect_tx.shared.b64 _, [%0], %1;" :: "r"(addr), "r"(bytes) : "memory")
#define MBAR_WAIT(addr, ph) do {                                                \
    uint32_t _m = (addr), _p = (ph), _d;                                        \
    asm volatile("{\n\t.reg .pred p;\n\t"                                       \
        "mbarrier.try_wait.parity.acquire.cta.shared::cta.b64 p, [%1], %2;\n\t" \
        "selp.b32 %0, 1, 0, p;\n\t}" : "=r"(_d) : "r"(_m), "r"(_p) : "memory"); \
    if (!_d) {                                                                  \
        asm volatile("{\n\t.reg .pred P;\n\tWL%=:\n\t"                          \
            "mbarrier.try_wait.parity.acquire.cta.shared::cta.b64 P, [%0], %1, 0x989680;\n\t" \
            "@P bra.uni WD%=;\n\tbra.uni WL%=;\n\tWD%=:\n\t}"                   \
            :: "r"(_m), "r"(_p) : "memory");                                    \
    }                                                                           \
} while (0)
static __device__ __forceinline__ void bulk_g2s(uint32_t dst, const void* src,
                                                uint32_t bytes, uint32_t mbar) {
    asm volatile(
        "cp.async.bulk.shared::cluster.global.mbarrier::complete_tx::bytes [%0], [%1], %2, [%3];"
        :: "r"(dst), "l"(src), "r"(bytes), "r"(mbar) : "memory");
}
static __device__ __forceinline__ void ldsm_x4(uint32_t& r0, uint32_t& r1, uint32_t& r2,
                                               uint32_t& r3, uint32_t addr) {
    asm volatile("ldmatrix.sync.aligned.m8n8.x4.shared.b16 {%0,%1,%2,%3}, [%4];"
                 : "=r"(r0), "=r"(r1), "=r"(r2), "=r"(r3) : "r"(addr));
}
static __device__ __forceinline__ void mma16816(float* d, const uint32_t* a, const uint32_t* b) {
    asm volatile(
        "mma.sync.aligned.m16n8k16.row.col.f32.f16.f16.f32 "
        "{%0,%1,%2,%3}, {%4,%5,%6,%7}, {%8,%9}, {%0,%1,%2,%3};"
        : "+f"(d[0]), "+f"(d[1]), "+f"(d[2]), "+f"(d[3])
        : "r"(a[0]), "r"(a[1]), "r"(a[2]), "r"(a[3]), "r"(b[0]), "r"(b[1]));
}

// ============================================================================
// Kernel 1: prep = first linear (blocks 0..511) + W2 quant/swizzle (512..1023)
// ============================================================================
__global__ void __launch_bounds__(256) k_prep(const float* __restrict__ x,
                                              const float* __restrict__ y,
                                              const float* __restrict__ W1,
                                              const float* __restrict__ b1,
                                              const float* __restrict__ W2) {
    int b = blockIdx.x;
    if (b >= 512) {
        int idx = ((b - 512) * 256 + threadIdx.x) * 2;
        int n = idx >> 9, h = idx & 511;
        int nc = n >> 7, n_local = n & 127;
        int kq = h >> 7, k_local = h & 127;
        int step = nc * 4 + kq;
        uint32_t c = (uint32_t)(k_local >> 3);
        uint32_t off = (uint32_t)n_local * 256 +
                       ((c ^ (uint32_t)(n_local & 7)) << 4) + (uint32_t)(k_local & 7) * 2;
        float2 v = *(const float2*)(W2 + (size_t)n * HH + h);
        __half2 hv;
        hv.x = __float2half_rn(v.x);
        hv.y = __float2half_rn(v.y);
        *(uint32_t*)(g_Wsw + (size_t)step * 32768 + off) = *(uint32_t*)&hv;
        return;
    }
    __shared__ float xs_t[128][33];
    __shared__ float ws[32][128];
    int path = b >> 8;
    int rem = b & 255;
    int i0 = (rem & 15) * 32, h0 = (rem >> 4) * 32;
    const float* src = path ? y : x;
    int colOff = path ? 128 : 0;

    for (int v = threadIdx.x; v < 32 * 128; v += 256) {
        int i = v >> 7, d = v & 127;
        xs_t[d][i] = src[(i0 + i) * 128 + d];
    }
    for (int v = threadIdx.x; v < 32 * 32; v += 256) {
        int r = v >> 5, c4 = v & 31;
        ((float4*)&ws[r][0])[c4] = ((const float4*)&W1[(h0 + r) * 256 + colOff])[c4];
    }
    __syncthreads();

    int ti = threadIdx.x & 31, th = threadIdx.x >> 5;
    float acc0 = 0.f, acc1 = 0.f, acc2 = 0.f, acc3 = 0.f;
    #pragma unroll 4
    for (int d = 0; d < 128; d++) {
        float xv = xs_t[d][ti];
        acc0 = fmaf(xv, ws[th * 4 + 0][d], acc0);
        acc1 = fmaf(xv, ws[th * 4 + 1][d], acc1);
        acc2 = fmaf(xv, ws[th * 4 + 2][d], acc2);
        acc3 = fmaf(xv, ws[th * 4 + 3][d], acc3);
    }
    float* dst = path ? g_hy : g_hx;
    int i = i0 + ti;
    int hb = h0 + th * 4;
    float a0 = path ? 0.f : b1[hb + 0];
    float a1 = path ? 0.f : b1[hb + 1];
    float a2 = path ? 0.f : b1[hb + 2];
    float a3 = path ? 0.f : b1[hb + 3];
    dst[i * HH + hb + 0] = acc0 + a0;
    dst[i * HH + hb + 1] = acc1 + a1;
    dst[i * HH + hb + 2] = acc2 + a2;
    dst[i * HH + hb + 3] = acc3 + a3;
}

// ============================================================================
// Kernel 2: main pair-GEMM + fused epilogue.  grid 2048, block 256 (8 warps)
//   CTA tile: 128 pairs (8i x 16j).  16 steps of 32KB W via cp.async.bulk,
//   2-deep; last-warp-to-finish issues the refetch (atomic counter, no
//   per-step __syncthreads).  Warp grid 2m x 4n, warp tile m64 x n32.
// ============================================================================
__global__ void __launch_bounds__(256, 1) k_main(const float* __restrict__ b2g,
                                                 const float* __restrict__ w3g,
                                                 const float* __restrict__ b3g,
                                                 float* __restrict__ out) {
    extern __shared__ __align__(1024) unsigned char smem[];
    uint32_t sb = smem_u32(smem);
    int tid = threadIdx.x, wid = tid >> 5, lane = tid & 31;
    int t = blockIdx.x;
    int i0 = (t >> 5) * 8, j0 = (t & 31) * 16;

    float* b2s = (float*)(smem + OFF_B2);
    float* w3s = (float*)(smem + OFF_W3);
    int* wcnt = (int*)(smem + OFF_MB + 16);

    // ---- init mbarriers/counters + kick off first two W slabs ----
    if (tid == 0) {
        MBAR_INIT(sb + OFF_MB + 0, 1);
        MBAR_INIT(sb + OFF_MB + 8, 1);
        wcnt[0] = 0;
        wcnt[1] = 0;
        asm volatile("fence.proxy.async.shared::cta;" ::: "memory");
        MBAR_EXPECT_TX(sb + OFF_MB + 0, 32768u);
        bulk_g2s(sb + OFF_W(0), g_Wsw + 0 * 32768, 32768u, sb + OFF_MB + 0);
        MBAR_EXPECT_TX(sb + OFF_MB + 8, 32768u);
        bulk_g2s(sb + OFF_W(1), g_Wsw + 1 * 32768, 32768u, sb + OFF_MB + 8);
    }

    // ---- b2 / w3 to SMEM ----
    for (int v = tid; v < 512; v += 256) {
        b2s[v] = b2g[v];
        w3s[v] = w3g[v];
    }

    // ---- build A = relu(hx_i + hy_j) fp16 (register-blocked: kk = tid) ----
    {
        int kk = tid;  // fixed half2 column per thread
        float2 hyv[16];
        #pragma unroll
        for (int j = 0; j < 16; j++)
            hyv[j] = ((const float2*)(g_hy + (j0 + j) * HH))[kk];
        uint32_t base = sb + OFF_A + (uint32_t)(kk & 3) * 4;
        uint32_t chunk = (uint32_t)(kk >> 2);
        #pragma unroll
        for (int ig = 0; ig < 8; ig++) {
            float2 hx2 = ((const float2*)(g_hx + (i0 + ig) * HH))[kk];
            #pragma unroll
            for (int j = 0; j < 16; j++) {
                float v0 = fmaxf(hx2.x + hyv[j].x, 0.f);
                float v1 = fmaxf(hx2.y + hyv[j].y, 0.f);
                __half2 hv;
                hv.x = __float2half_rn(v0);
                hv.y = __float2half_rn(v1);
                uint32_t p = (uint32_t)(ig * 16 + j);
                uint32_t addr = base + p * 1024 + ((chunk ^ (p & 7)) << 4);
                asm volatile("st.shared.b32 [%0], %1;"
                             :: "r"(addr), "r"(*(uint32_t*)&hv) : "memory");
            }
        }
    }
    __syncthreads();   // A ready; mbarrier/counter inits visible

    // ---- per-warp geometry: warp tile m64 x n32 ----
    int wm = wid >> 2;          // 0..1 -> m0 = wm*64
    int wn = wid & 3;           // 0..3 -> n0 = wn*32 within 128-chunk
    int m0 = wm * 64, n0 = wn * 32;

    uint32_t x7 = (uint32_t)(lane & 7);
    uint32_t aHi = (uint32_t)(lane >> 4);
    uint32_t aRow[4];
    #pragma unroll
    for (int mi = 0; mi < 4; mi++)
        aRow[mi] = sb + OFF_A + (uint32_t)(m0 + mi * 16 + (lane & 15)) * 1024;
    uint32_t bRowOff = (uint32_t)(n0 + (lane & 7) + ((lane >> 4) << 3)) * 256;
    uint32_t bHi = (uint32_t)((lane >> 3) & 1);

    float d[4][4][4];                 // [mi][ni][q]
    float rowacc[4][2];               // [mi][row half]
    #pragma unroll
    for (int mi = 0; mi < 4; mi++) { rowacc[mi][0] = 0.f; rowacc[mi][1] = 0.f; }

    #pragma unroll 1
    for (int st = 0; st < 16; st++) {
        int s = st & 1, kq = st & 3;
        MBAR_WAIT(sb + OFF_MB + s * 8, (st >> 1) & 1);

        if (kq == 0) {
            #pragma unroll
            for (int mi = 0; mi < 4; mi++)
                #pragma unroll
                for (int ni = 0; ni < 4; ni++)
                    #pragma unroll
                    for (int q = 0; q < 4; q++) d[mi][ni][q] = 0.f;
        }

        uint32_t bBase = sb + OFF_W(s) + bRowOff;
        uint32_t aChunk0 = (uint32_t)(kq * 16);

        #pragma unroll
        for (int kk = 0; kk < 8; kk++) {
            uint32_t aswz = (((aChunk0 + (uint32_t)(kk << 1) + aHi) ^ x7) << 4);
            uint32_t bswz = ((((uint32_t)(kk << 1) + bHi) ^ x7) << 4);
            uint32_t a[4][4], b0[4], b1[4];
            #pragma unroll
            for (int mi = 0; mi < 4; mi++)
                ldsm_x4(a[mi][0], a[mi][1], a[mi][2], a[mi][3], aRow[mi] + aswz);
            ldsm_x4(b0[0], b0[1], b0[2], b0[3], bBase + bswz);
            ldsm_x4(b1[0], b1[1], b1[2], b1[3], bBase + 16 * 256 + bswz);
            #pragma unroll
            for (int mi = 0; mi < 4; mi++) {
                mma16816(d[mi][0], a[mi], b0 + 0);
                mma16816(d[mi][1], a[mi], b0 + 2);
                mma16816(d[mi][2], a[mi], b1 + 0);
                mma16816(d[mi][3], a[mi], b1 + 2);
            }
        }

        if (kq == 3) {
            int ncol = (st >> 2) * 128 + n0 + (lane & 3) * 2;
            #pragma unroll
            for (int ni = 0; ni < 4; ni++) {
                int c0 = ncol + ni * 8, c1 = c0 + 1;
                float bb0 = b2s[c0], bb1 = b2s[c1];
                float ww0 = w3s[c0], ww1 = w3s[c1];
                #pragma unroll
                for (int mi = 0; mi < 4; mi++) {
                    rowacc[mi][0] = fmaf(fmaxf(d[mi][ni][0] + bb0, 0.f), ww0, rowacc[mi][0]);
                    rowacc[mi][0] = fmaf(fmaxf(d[mi][ni][1] + bb1, 0.f), ww1, rowacc[mi][0]);
                    rowacc[mi][1] = fmaf(fmaxf(d[mi][ni][2] + bb0, 0.f), ww0, rowacc[mi][1]);
                    rowacc[mi][1] = fmaf(fmaxf(d[mi][ni][3] + bb1, 0.f), ww1, rowacc[mi][1]);
                }
            }
        }

        // last warp to finish this step issues the refetch into this slab
        if (lane == 0) {
            int old;
            asm volatile("atom.shared.add.s32 %0, [%1], 1;"
                         : "=r"(old) : "r"(sb + OFF_MB + 16 + s * 4) : "memory");
            if ((old & 7) == 7 && st + 2 < 16) {
                MBAR_EXPECT_TX(sb + OFF_MB + s * 8, 32768u);
                bulk_g2s(sb + OFF_W(s), g_Wsw + (size_t)(st + 2) * 32768, 32768u,
                         sb + OFF_MB + s * 8);
            }
        }
    }

    // ---- reduce across 4 lanes sharing each row, then across 4 n-warps ----
    #pragma unroll
    for (int mi = 0; mi < 4; mi++)
        #pragma unroll
        for (int rh = 0; rh < 2; rh++) {
            rowacc[mi][rh] += __shfl_xor_sync(0xFFFFFFFFu, rowacc[mi][rh], 1);
            rowacc[mi][rh] += __shfl_xor_sync(0xFFFFFFFFu, rowacc[mi][rh], 2);
        }

    __syncthreads();   // all warps out of the main loop before reusing W(0)

    float* part = (float*)(smem + OFF_W(0));  // reuse: [128][4]
    if ((lane & 3) == 0) {
        int g = lane >> 2;
        #pragma unroll
        for (int mi = 0; mi < 4; mi++)
            #pragma unroll
            for (int rh = 0; rh < 2; rh++) {
                int m = m0 + mi * 16 + rh * 8 + g;
                part[m * 4 + wn] = rowacc[mi][rh];
            }
    }
    __syncthreads();

    if (tid < 128) {
        float res = part[tid * 4 + 0] + part[tid * 4 + 1] +
                    part[tid * 4 + 2] + part[tid * 4 + 3] + b3g[0];
        int i = i0 + (tid >> 4);
        int j = j0 + (tid & 15);
        out[i * BB + j] = res;
    }
}

// ============================================================================
// Host launcher
// ============================================================================
extern "C" void kernel_launch(void* const* d_in, const int* in_sizes, int n_in,
                              void* d_out, int out_size) {
    const float* x  = (const float*)d_in[0];
    const float* y  = (const float*)d_in[1];
    const float* W1 = (const float*)d_in[2];
    const float* b1 = (const float*)d_in[3];
    const float* W2 = (const float*)d_in[4];
    const float* b2 = (const float*)d_in[5];
    const float* W3 = (const float*)d_in[6];
    const float* b3 = (const float*)d_in[7];
    float* out = (float*)d_out;

    cudaFuncSetAttribute(k_main, cudaFuncAttributeMaxDynamicSharedMemorySize, SMEM_BYTES);

    k_prep<<<1024, 256>>>(x, y, W1, b1, W2);
    k_main<<<2048, 256, SMEM_BYTES>>>(b2, W3, b3, out);
}